// round 1
// baseline (speedup 1.0000x reference)
#include <cuda_runtime.h>
#include <math.h>

#define NN 50000          // nodes
#define NE 800000         // edges
#define NT (NN + NE)      // edges + self loops
#define HC 256            // HEADS*OUT_CH
#define NEG_SLOPE 0.2f

// ---------------- device scratch (no allocations allowed) ----------------
__device__ __align__(16) float g_h[NN * HC];     // current layer h = x @ W
__device__ __align__(16) float g_mid[NN * HC];   // layer-1 output (ELU'd)
__device__ __align__(16) float g_asrc[NN * 4];   // per-node, per-head src logits
__device__ __align__(16) float g_adst[NN * 4];
__device__ int g_cnt[NN];
__device__ int g_cursor[NN];
__device__ int g_start[NN + 1];
__device__ int g_srcsorted[NT];

// ---------------- small helpers ----------------
__device__ __forceinline__ float leaky(float x) { return x > 0.f ? x : NEG_SLOPE * x; }

// ---------------- edge sort: histogram / scan / scatter ----------------
__global__ void zero_kernel() {
    int i = blockIdx.x * blockDim.x + threadIdx.x;
    if (i < NN) { g_cnt[i] = 0; g_cursor[i] = 0; }
}

__global__ void hist_kernel(const int* __restrict__ ei) {
    int i = blockIdx.x * blockDim.x + threadIdx.x;
    if (i >= NT) return;
    int d = (i < NE) ? ei[NE + i] : (i - NE);
    atomicAdd(&g_cnt[d], 1);
}

// single-block exclusive scan over g_cnt -> g_start (n = NN), 1024 threads
__global__ void scan_kernel() {
    __shared__ int warp_sums[32];
    __shared__ int s_carry;
    int tid = threadIdx.x, lane = tid & 31, wid = tid >> 5;
    if (tid == 0) s_carry = 0;
    __syncthreads();
    for (int base = 0; base < NN; base += 1024) {
        int i = base + tid;
        int v = (i < NN) ? g_cnt[i] : 0;
        int x = v;
        #pragma unroll
        for (int o = 1; o < 32; o <<= 1) {
            int y = __shfl_up_sync(0xFFFFFFFFu, x, o);
            if (lane >= o) x += y;
        }
        if (lane == 31) warp_sums[wid] = x;
        __syncthreads();
        if (wid == 0) {
            int s = warp_sums[lane];
            #pragma unroll
            for (int o = 1; o < 32; o <<= 1) {
                int y = __shfl_up_sync(0xFFFFFFFFu, s, o);
                if (lane >= o) s += y;
            }
            warp_sums[lane] = s;  // inclusive warp totals
        }
        __syncthreads();
        int warp_off = (wid > 0) ? warp_sums[wid - 1] : 0;
        int excl = x - v + warp_off + s_carry;
        if (i < NN) g_start[i] = excl;
        int carry_new = s_carry + warp_sums[31];
        __syncthreads();
        if (tid == 0) s_carry = carry_new;
        __syncthreads();
    }
    if (threadIdx.x == 0) g_start[NN] = s_carry;
}

__global__ void scatter_kernel(const int* __restrict__ ei) {
    int i = blockIdx.x * blockDim.x + threadIdx.x;
    if (i >= NT) return;
    int s, d;
    if (i < NE) { s = ei[i]; d = ei[NE + i]; }
    else        { s = d = i - NE; }
    int pos = g_start[d] + atomicAdd(&g_cursor[d], 1);
    g_srcsorted[pos] = s;
}

// ---------------- SGEMM: C[M,256] = A[M,256] @ B[256,256] ----------------
// BM=64, full N=256 per block, BK=16, 256 threads, 8x8 outputs/thread.
__global__ void __launch_bounds__(256) gemm256_kernel(
    const float* __restrict__ A, const float* __restrict__ B,
    float* __restrict__ C, int M)
{
    __shared__ float As[16][65];     // padded
    __shared__ float Bs[16][256];
    int tid = threadIdx.x;
    int tx = tid & 31;               // col octet: cols tx*8 .. tx*8+7
    int ty = tid >> 5;               // row group: rows ty + 8*i
    int row0 = blockIdx.x * 64;

    float4 acc0[8], acc1[8];
    #pragma unroll
    for (int i = 0; i < 8; i++) {
        acc0[i] = make_float4(0.f, 0.f, 0.f, 0.f);
        acc1[i] = make_float4(0.f, 0.f, 0.f, 0.f);
    }

    for (int k0 = 0; k0 < 256; k0 += 16) {
        // A tile: 64 rows x 16 k, one float4 per thread
        {
            int r = tid >> 2;
            int kc = (tid & 3) * 4;
            int gr = row0 + r;
            float4 v = (gr < M) ? *(const float4*)(A + (size_t)gr * 256 + k0 + kc)
                                : make_float4(0.f, 0.f, 0.f, 0.f);
            As[kc + 0][r] = v.x; As[kc + 1][r] = v.y;
            As[kc + 2][r] = v.z; As[kc + 3][r] = v.w;
        }
        // B tile: 16 rows x 256 cols, 4 float4 per thread
        #pragma unroll
        for (int u = 0; u < 4; u++) {
            int idx = tid + u * 256;      // 0..1023 float4 slots
            int br = idx >> 6;            // 0..15
            int bc = (idx & 63) * 4;      // 0..252
            *(float4*)&Bs[br][bc] = *(const float4*)(B + (size_t)(k0 + br) * 256 + bc);
        }
        __syncthreads();

        #pragma unroll
        for (int k = 0; k < 16; k++) {
            float4 b0 = *(const float4*)&Bs[k][tx * 8];
            float4 b1 = *(const float4*)&Bs[k][tx * 8 + 4];
            #pragma unroll
            for (int i = 0; i < 8; i++) {
                float a = As[k][ty + 8 * i];
                acc0[i].x += a * b0.x; acc0[i].y += a * b0.y;
                acc0[i].z += a * b0.z; acc0[i].w += a * b0.w;
                acc1[i].x += a * b1.x; acc1[i].y += a * b1.y;
                acc1[i].z += a * b1.z; acc1[i].w += a * b1.w;
            }
        }
        __syncthreads();
    }

    #pragma unroll
    for (int i = 0; i < 8; i++) {
        int gr = row0 + ty + 8 * i;
        if (gr < M) {
            *(float4*)(C + (size_t)gr * 256 + tx * 8)     = acc0[i];
            *(float4*)(C + (size_t)gr * 256 + tx * 8 + 4) = acc1[i];
        }
    }
}

// ---------------- attention dot products ----------------
// one warp per (node, head): a_src[n,h] = <h[n,h,:], att_src[h,:]>, same for dst
__global__ void dots_kernel(const float* __restrict__ h,
                            const float* __restrict__ att_s,
                            const float* __restrict__ att_d)
{
    int w = (blockIdx.x * blockDim.x + threadIdx.x) >> 5;
    int lane = threadIdx.x & 31;
    if (w >= NN * 4) return;
    int n = w >> 2, hd = w & 3;
    const float* hp = h + (size_t)n * HC + hd * 64;
    float v0 = hp[lane], v1 = hp[32 + lane];
    float s0 = att_s[hd * 64 + lane], s1 = att_s[hd * 64 + 32 + lane];
    float d0 = att_d[hd * 64 + lane], d1 = att_d[hd * 64 + 32 + lane];
    float as = v0 * s0 + v1 * s1;
    float ad = v0 * d0 + v1 * d1;
    #pragma unroll
    for (int o = 16; o; o >>= 1) {
        as += __shfl_xor_sync(0xFFFFFFFFu, as, o);
        ad += __shfl_xor_sync(0xFFFFFFFFu, ad, o);
    }
    if (lane == 0) { g_asrc[w] = as; g_adst[w] = ad; }
}

// ---------------- fused segment softmax + aggregation + bias + ELU ----------------
// one warp per destination node; edges pre-sorted by dst; zero atomics.
__global__ void __launch_bounds__(256) node_kernel(
    const float* __restrict__ h, const float* __restrict__ bias,
    float* __restrict__ out)
{
    int w = (blockIdx.x * blockDim.x + threadIdx.x) >> 5;
    int lane = threadIdx.x & 31;
    if (w >= NN) return;
    int d = w;
    int start = g_start[d], end = g_start[d + 1];

    float4 ad4 = *(const float4*)(g_adst + d * 4);

    // pass 1: per-head max of leaky(a_src[s] + a_dst[d])
    float4 m = make_float4(-INFINITY, -INFINITY, -INFINITY, -INFINITY);
    for (int j0 = start; j0 < end; j0 += 32) {
        int j = j0 + lane;
        if (j < end) {
            int s = g_srcsorted[j];
            float4 a = *(const float4*)(g_asrc + s * 4);
            m.x = fmaxf(m.x, leaky(a.x + ad4.x));
            m.y = fmaxf(m.y, leaky(a.y + ad4.y));
            m.z = fmaxf(m.z, leaky(a.z + ad4.z));
            m.w = fmaxf(m.w, leaky(a.w + ad4.w));
        }
    }
    #pragma unroll
    for (int o = 16; o; o >>= 1) {
        m.x = fmaxf(m.x, __shfl_xor_sync(0xFFFFFFFFu, m.x, o));
        m.y = fmaxf(m.y, __shfl_xor_sync(0xFFFFFFFFu, m.y, o));
        m.z = fmaxf(m.z, __shfl_xor_sync(0xFFFFFFFFu, m.z, o));
        m.w = fmaxf(m.w, __shfl_xor_sync(0xFFFFFFFFu, m.w, o));
    }

    // pass 2: per-head sum of exp(e - max)
    float4 sum = make_float4(0.f, 0.f, 0.f, 0.f);
    for (int j0 = start; j0 < end; j0 += 32) {
        int j = j0 + lane;
        if (j < end) {
            int s = g_srcsorted[j];
            float4 a = *(const float4*)(g_asrc + s * 4);
            sum.x += expf(leaky(a.x + ad4.x) - m.x);
            sum.y += expf(leaky(a.y + ad4.y) - m.y);
            sum.z += expf(leaky(a.z + ad4.z) - m.z);
            sum.w += expf(leaky(a.w + ad4.w) - m.w);
        }
    }
    #pragma unroll
    for (int o = 16; o; o >>= 1) {
        sum.x += __shfl_xor_sync(0xFFFFFFFFu, sum.x, o);
        sum.y += __shfl_xor_sync(0xFFFFFFFFu, sum.y, o);
        sum.z += __shfl_xor_sync(0xFFFFFFFFu, sum.z, o);
        sum.w += __shfl_xor_sync(0xFFFFFFFFu, sum.w, o);
    }
    float4 inv;
    inv.x = 1.f / (sum.x + 1e-16f); inv.y = 1.f / (sum.y + 1e-16f);
    inv.z = 1.f / (sum.z + 1e-16f); inv.w = 1.f / (sum.w + 1e-16f);

    // per-lane head view: lane handles channels [lane*8, lane*8+8) -> head = lane>>3
    int head = lane >> 3;
    float mh   = (head == 0) ? m.x   : (head == 1) ? m.y   : (head == 2) ? m.z   : m.w;
    float invh = (head == 0) ? inv.x : (head == 1) ? inv.y : (head == 2) ? inv.z : inv.w;
    float adh  = (head == 0) ? ad4.x : (head == 1) ? ad4.y : (head == 2) ? ad4.z : ad4.w;

    // pass 3: aggregate messages, all 32 lanes cooperate per edge
    float4 acc0 = make_float4(0.f, 0.f, 0.f, 0.f);
    float4 acc1 = make_float4(0.f, 0.f, 0.f, 0.f);
    for (int j = start; j < end; ++j) {
        int s = g_srcsorted[j];                 // uniform across warp
        float e = leaky(g_asrc[s * 4 + head] + adh);
        float wgt = expf(e - mh) * invh;
        const float4* hp = (const float4*)(h + (size_t)s * HC + lane * 8);
        float4 p0 = hp[0], p1 = hp[1];
        acc0.x += p0.x * wgt; acc0.y += p0.y * wgt;
        acc0.z += p0.z * wgt; acc0.w += p0.w * wgt;
        acc1.x += p1.x * wgt; acc1.y += p1.y * wgt;
        acc1.z += p1.z * wgt; acc1.w += p1.w * wgt;
    }

    // bias + ELU + store
    const float4* b4 = (const float4*)(bias + lane * 8);
    float4 b0 = b4[0], b1 = b4[1];
    float o0[8] = {acc0.x + b0.x, acc0.y + b0.y, acc0.z + b0.z, acc0.w + b0.w,
                   acc1.x + b1.x, acc1.y + b1.y, acc1.z + b1.z, acc1.w + b1.w};
    #pragma unroll
    for (int q = 0; q < 8; q++) o0[q] = (o0[q] > 0.f) ? o0[q] : expm1f(o0[q]);
    float4 r0 = make_float4(o0[0], o0[1], o0[2], o0[3]);
    float4 r1 = make_float4(o0[4], o0[5], o0[6], o0[7]);
    *(float4*)(out + (size_t)d * HC + lane * 8)     = r0;
    *(float4*)(out + (size_t)d * HC + lane * 8 + 4) = r1;
}

// ---------------- launch ----------------
extern "C" void kernel_launch(void* const* d_in, const int* in_sizes, int n_in,
                              void* d_out, int out_size)
{
    const float* x   = (const float*)d_in[0];
    const int*   ei  = (const int*)  d_in[1];
    const float* W1  = (const float*)d_in[2];
    const float* as1 = (const float*)d_in[3];
    const float* ad1 = (const float*)d_in[4];
    const float* b1  = (const float*)d_in[5];
    const float* W2  = (const float*)d_in[6];
    const float* as2 = (const float*)d_in[7];
    const float* ad2 = (const float*)d_in[8];
    const float* b2  = (const float*)d_in[9];
    float* out = (float*)d_out;

    float* g_h_p;    cudaGetSymbolAddress((void**)&g_h_p,   g_h);
    float* g_mid_p;  cudaGetSymbolAddress((void**)&g_mid_p, g_mid);

    // edge sort by dst (layer-invariant; computed every launch for determinism)
    zero_kernel<<<(NN + 255) / 256, 256>>>();
    hist_kernel<<<(NT + 255) / 256, 256>>>(ei);
    scan_kernel<<<1, 1024>>>();
    scatter_kernel<<<(NT + 255) / 256, 256>>>(ei);

    const int gemm_blocks = (NN + 63) / 64;
    const int dot_blocks  = (NN * 4 * 32 + 255) / 256;
    const int node_blocks = (NN * 32 + 255) / 256;

    // layer 1
    gemm256_kernel<<<gemm_blocks, 256>>>(x, W1, g_h_p, NN);
    dots_kernel<<<dot_blocks, 256>>>(g_h_p, as1, ad1);
    node_kernel<<<node_blocks, 256>>>(g_h_p, b1, g_mid_p);

    // layer 2
    gemm256_kernel<<<gemm_blocks, 256>>>(g_mid_p, W2, g_h_p, NN);
    dots_kernel<<<dot_blocks, 256>>>(g_h_p, as2, ad2);
    node_kernel<<<node_blocks, 256>>>(g_h_p, b2, out);
}

// round 2
// speedup vs baseline: 1.6110x; 1.6110x over previous
#include <cuda_runtime.h>
#include <math.h>

#define NN 50000          // nodes
#define NE 800000         // edges
#define NT (NN + NE)      // edges + self loops
#define HC 256            // HEADS*OUT_CH
#define NEG_SLOPE 0.2f

// ---------------- device scratch (no allocations allowed) ----------------
__device__ __align__(16) float g_h[NN * HC];     // current layer h = x @ W
__device__ __align__(16) float g_mid[NN * HC];   // layer-1 output (ELU'd)
__device__ __align__(16) float g_asrc[NN * 4];   // per-node, per-head src logits
__device__ __align__(16) float g_adst[NN * 4];
__device__ int g_cnt[NN];
__device__ int g_cursor[NN];
__device__ int g_start[NN + 1];
__device__ int g_srcsorted[NT];

// ---------------- small helpers ----------------
__device__ __forceinline__ float leaky(float x) { return x > 0.f ? x : NEG_SLOPE * x; }

__device__ __forceinline__ unsigned f2tf32(float f) {
    unsigned u;
    asm volatile("cvt.rna.tf32.f32 %0, %1;" : "=r"(u) : "f"(f));
    return u;
}

// ---------------- edge sort: histogram / scan / scatter ----------------
__global__ void zero_kernel() {
    int i = blockIdx.x * blockDim.x + threadIdx.x;
    if (i < NN) { g_cnt[i] = 0; g_cursor[i] = 0; }
}

__global__ void hist_kernel(const int* __restrict__ ei) {
    int i = blockIdx.x * blockDim.x + threadIdx.x;
    if (i >= NT) return;
    int d = (i < NE) ? ei[NE + i] : (i - NE);
    atomicAdd(&g_cnt[d], 1);
}

// single-block exclusive scan over g_cnt -> g_start (n = NN), 1024 threads
__global__ void scan_kernel() {
    __shared__ int warp_sums[32];
    __shared__ int s_carry;
    int tid = threadIdx.x, lane = tid & 31, wid = tid >> 5;
    if (tid == 0) s_carry = 0;
    __syncthreads();
    for (int base = 0; base < NN; base += 1024) {
        int i = base + tid;
        int v = (i < NN) ? g_cnt[i] : 0;
        int x = v;
        #pragma unroll
        for (int o = 1; o < 32; o <<= 1) {
            int y = __shfl_up_sync(0xFFFFFFFFu, x, o);
            if (lane >= o) x += y;
        }
        if (lane == 31) warp_sums[wid] = x;
        __syncthreads();
        if (wid == 0) {
            int s = warp_sums[lane];
            #pragma unroll
            for (int o = 1; o < 32; o <<= 1) {
                int y = __shfl_up_sync(0xFFFFFFFFu, s, o);
                if (lane >= o) s += y;
            }
            warp_sums[lane] = s;  // inclusive warp totals
        }
        __syncthreads();
        int warp_off = (wid > 0) ? warp_sums[wid - 1] : 0;
        int excl = x - v + warp_off + s_carry;
        if (i < NN) g_start[i] = excl;
        int carry_new = s_carry + warp_sums[31];
        __syncthreads();
        if (tid == 0) s_carry = carry_new;
        __syncthreads();
    }
    if (threadIdx.x == 0) g_start[NN] = s_carry;
}

__global__ void scatter_kernel(const int* __restrict__ ei) {
    int i = blockIdx.x * blockDim.x + threadIdx.x;
    if (i >= NT) return;
    int s, d;
    if (i < NE) { s = ei[i]; d = ei[NE + i]; }
    else        { s = d = i - NE; }
    int pos = g_start[d] + atomicAdd(&g_cursor[d], 1);
    g_srcsorted[pos] = s;
}

// ---------------- tf32 tensor-core GEMM: C[M,256] = A[M,256] @ B[256,256] ----
// BM=128, BN=128, BK=32, 256 threads (8 warps, 4x2), warp tile 32x64.
// m16n8k8 tf32 mma; A/B converted to tf32 (RNA) on the smem-store path.
#define GBM 128
#define GBN 128
#define GBK 32

__global__ void __launch_bounds__(256, 1) gemm_tf32_kernel(
    const float* __restrict__ A, const float* __restrict__ B,
    float* __restrict__ C, int M)
{
    __shared__ float As[GBM][GBK + 4];   // [128][36]
    __shared__ float Bs[GBK][GBN + 4];   // [32][132]

    int tid = threadIdx.x;
    int warp = tid >> 5, lane = tid & 31;
    int wm = warp & 3;        // warp M index 0..3
    int wn = warp >> 2;       // warp N index 0..1
    int g = lane >> 2;        // groupID 0..7
    int t = lane & 3;         // threadInGroup 0..3

    int row0 = blockIdx.x * GBM;
    int col0 = blockIdx.y * GBN;

    float c[2][8][4];
    #pragma unroll
    for (int i = 0; i < 2; i++)
        #pragma unroll
        for (int j = 0; j < 8; j++)
            #pragma unroll
            for (int q = 0; q < 4; q++) c[i][j][q] = 0.f;

    float4 pa[4], pb[4];

    // prologue: load chunk 0
    #pragma unroll
    for (int u = 0; u < 4; u++) {
        int slot = tid + u * 256;
        int r = slot >> 3, c4 = (slot & 7) << 2;
        int gr = row0 + r;
        pa[u] = (gr < M) ? *(const float4*)(A + (size_t)gr * 256 + c4)
                         : make_float4(0.f, 0.f, 0.f, 0.f);
        int br = slot >> 5, bc4 = (slot & 31) << 2;
        pb[u] = *(const float4*)(B + (size_t)br * 256 + col0 + bc4);
    }

    for (int kk = 0; kk < 256; kk += GBK) {
        // deposit prefetched chunk into smem (tf32-converted)
        #pragma unroll
        for (int u = 0; u < 4; u++) {
            int slot = tid + u * 256;
            int r = slot >> 3, c4 = (slot & 7) << 2;
            float4 v = pa[u];
            float4 w;
            w.x = __uint_as_float(f2tf32(v.x));
            w.y = __uint_as_float(f2tf32(v.y));
            w.z = __uint_as_float(f2tf32(v.z));
            w.w = __uint_as_float(f2tf32(v.w));
            *(float4*)&As[r][c4] = w;
            int br = slot >> 5, bc4 = (slot & 31) << 2;
            float4 b = pb[u];
            float4 bw;
            bw.x = __uint_as_float(f2tf32(b.x));
            bw.y = __uint_as_float(f2tf32(b.y));
            bw.z = __uint_as_float(f2tf32(b.z));
            bw.w = __uint_as_float(f2tf32(b.w));
            *(float4*)&Bs[br][bc4] = bw;
        }
        __syncthreads();

        // prefetch next chunk
        if (kk + GBK < 256) {
            #pragma unroll
            for (int u = 0; u < 4; u++) {
                int slot = tid + u * 256;
                int r = slot >> 3, c4 = (slot & 7) << 2;
                int gr = row0 + r;
                pa[u] = (gr < M) ? *(const float4*)(A + (size_t)gr * 256 + kk + GBK + c4)
                                 : make_float4(0.f, 0.f, 0.f, 0.f);
                int br = slot >> 5, bc4 = (slot & 31) << 2;
                pb[u] = *(const float4*)(B + (size_t)(kk + GBK + br) * 256 + col0 + bc4);
            }
        }

        // compute on this chunk
        #pragma unroll
        for (int ks = 0; ks < GBK; ks += 8) {
            unsigned af[2][4];
            #pragma unroll
            for (int i = 0; i < 2; i++) {
                int m = wm * 32 + i * 16;
                af[i][0] = __float_as_uint(As[m + g][ks + t]);
                af[i][1] = __float_as_uint(As[m + 8 + g][ks + t]);
                af[i][2] = __float_as_uint(As[m + g][ks + t + 4]);
                af[i][3] = __float_as_uint(As[m + 8 + g][ks + t + 4]);
            }
            unsigned bf[8][2];
            #pragma unroll
            for (int j = 0; j < 8; j++) {
                int n = wn * 64 + j * 8;
                bf[j][0] = __float_as_uint(Bs[ks + t][n + g]);
                bf[j][1] = __float_as_uint(Bs[ks + t + 4][n + g]);
            }
            #pragma unroll
            for (int i = 0; i < 2; i++) {
                #pragma unroll
                for (int j = 0; j < 8; j++) {
                    asm volatile(
                        "mma.sync.aligned.m16n8k8.row.col.f32.tf32.tf32.f32 "
                        "{%0,%1,%2,%3}, {%4,%5,%6,%7}, {%8,%9}, {%0,%1,%2,%3};\n"
                        : "+f"(c[i][j][0]), "+f"(c[i][j][1]),
                          "+f"(c[i][j][2]), "+f"(c[i][j][3])
                        : "r"(af[i][0]), "r"(af[i][1]), "r"(af[i][2]), "r"(af[i][3]),
                          "r"(bf[j][0]), "r"(bf[j][1]));
                }
            }
        }
        __syncthreads();
    }

    // epilogue
    #pragma unroll
    for (int i = 0; i < 2; i++) {
        #pragma unroll
        for (int j = 0; j < 8; j++) {
            int r0 = row0 + wm * 32 + i * 16 + g;
            int cc = col0 + wn * 64 + j * 8 + 2 * t;
            if (r0 < M)
                *(float2*)(C + (size_t)r0 * 256 + cc) = make_float2(c[i][j][0], c[i][j][1]);
            int r1 = r0 + 8;
            if (r1 < M)
                *(float2*)(C + (size_t)r1 * 256 + cc) = make_float2(c[i][j][2], c[i][j][3]);
        }
    }
}

// ---------------- attention dot products ----------------
__global__ void dots_kernel(const float* __restrict__ h,
                            const float* __restrict__ att_s,
                            const float* __restrict__ att_d)
{
    int w = (blockIdx.x * blockDim.x + threadIdx.x) >> 5;
    int lane = threadIdx.x & 31;
    if (w >= NN * 4) return;
    int n = w >> 2, hd = w & 3;
    const float* hp = h + (size_t)n * HC + hd * 64;
    float v0 = hp[lane], v1 = hp[32 + lane];
    float s0 = att_s[hd * 64 + lane], s1 = att_s[hd * 64 + 32 + lane];
    float d0 = att_d[hd * 64 + lane], d1 = att_d[hd * 64 + 32 + lane];
    float as = v0 * s0 + v1 * s1;
    float ad = v0 * d0 + v1 * d1;
    #pragma unroll
    for (int o = 16; o; o >>= 1) {
        as += __shfl_xor_sync(0xFFFFFFFFu, as, o);
        ad += __shfl_xor_sync(0xFFFFFFFFu, ad, o);
    }
    if (lane == 0) { g_asrc[w] = as; g_adst[w] = ad; }
}

// ---------------- fused segment softmax + aggregation + bias + ELU ----------------
__global__ void __launch_bounds__(256) node_kernel(
    const float* __restrict__ h, const float* __restrict__ bias,
    float* __restrict__ out)
{
    int w = (blockIdx.x * blockDim.x + threadIdx.x) >> 5;
    int lane = threadIdx.x & 31;
    if (w >= NN) return;
    int d = w;
    int start = g_start[d], end = g_start[d + 1];

    float4 ad4 = *(const float4*)(g_adst + d * 4);

    // pass 1: per-head max
    float4 m = make_float4(-INFINITY, -INFINITY, -INFINITY, -INFINITY);
    for (int j0 = start; j0 < end; j0 += 32) {
        int j = j0 + lane;
        if (j < end) {
            int s = g_srcsorted[j];
            float4 a = *(const float4*)(g_asrc + s * 4);
            m.x = fmaxf(m.x, leaky(a.x + ad4.x));
            m.y = fmaxf(m.y, leaky(a.y + ad4.y));
            m.z = fmaxf(m.z, leaky(a.z + ad4.z));
            m.w = fmaxf(m.w, leaky(a.w + ad4.w));
        }
    }
    #pragma unroll
    for (int o = 16; o; o >>= 1) {
        m.x = fmaxf(m.x, __shfl_xor_sync(0xFFFFFFFFu, m.x, o));
        m.y = fmaxf(m.y, __shfl_xor_sync(0xFFFFFFFFu, m.y, o));
        m.z = fmaxf(m.z, __shfl_xor_sync(0xFFFFFFFFu, m.z, o));
        m.w = fmaxf(m.w, __shfl_xor_sync(0xFFFFFFFFu, m.w, o));
    }

    // pass 2: per-head sum of exp
    float4 sum = make_float4(0.f, 0.f, 0.f, 0.f);
    for (int j0 = start; j0 < end; j0 += 32) {
        int j = j0 + lane;
        if (j < end) {
            int s = g_srcsorted[j];
            float4 a = *(const float4*)(g_asrc + s * 4);
            sum.x += expf(leaky(a.x + ad4.x) - m.x);
            sum.y += expf(leaky(a.y + ad4.y) - m.y);
            sum.z += expf(leaky(a.z + ad4.z) - m.z);
            sum.w += expf(leaky(a.w + ad4.w) - m.w);
        }
    }
    #pragma unroll
    for (int o = 16; o; o >>= 1) {
        sum.x += __shfl_xor_sync(0xFFFFFFFFu, sum.x, o);
        sum.y += __shfl_xor_sync(0xFFFFFFFFu, sum.y, o);
        sum.z += __shfl_xor_sync(0xFFFFFFFFu, sum.z, o);
        sum.w += __shfl_xor_sync(0xFFFFFFFFu, sum.w, o);
    }
    float4 inv;
    inv.x = 1.f / (sum.x + 1e-16f); inv.y = 1.f / (sum.y + 1e-16f);
    inv.z = 1.f / (sum.z + 1e-16f); inv.w = 1.f / (sum.w + 1e-16f);

    int head = lane >> 3;
    float mh   = (head == 0) ? m.x   : (head == 1) ? m.y   : (head == 2) ? m.z   : m.w;
    float invh = (head == 0) ? inv.x : (head == 1) ? inv.y : (head == 2) ? inv.z : inv.w;
    float adh  = (head == 0) ? ad4.x : (head == 1) ? ad4.y : (head == 2) ? ad4.z : ad4.w;

    // pass 3: aggregate messages
    float4 acc0 = make_float4(0.f, 0.f, 0.f, 0.f);
    float4 acc1 = make_float4(0.f, 0.f, 0.f, 0.f);
    for (int j = start; j < end; ++j) {
        int s = g_srcsorted[j];
        float e = leaky(g_asrc[s * 4 + head] + adh);
        float wgt = expf(e - mh) * invh;
        const float4* hp = (const float4*)(h + (size_t)s * HC + lane * 8);
        float4 p0 = hp[0], p1 = hp[1];
        acc0.x += p0.x * wgt; acc0.y += p0.y * wgt;
        acc0.z += p0.z * wgt; acc0.w += p0.w * wgt;
        acc1.x += p1.x * wgt; acc1.y += p1.y * wgt;
        acc1.z += p1.z * wgt; acc1.w += p1.w * wgt;
    }

    const float4* b4 = (const float4*)(bias + lane * 8);
    float4 b0 = b4[0], b1 = b4[1];
    float o0[8] = {acc0.x + b0.x, acc0.y + b0.y, acc0.z + b0.z, acc0.w + b0.w,
                   acc1.x + b1.x, acc1.y + b1.y, acc1.z + b1.z, acc1.w + b1.w};
    #pragma unroll
    for (int q = 0; q < 8; q++) o0[q] = (o0[q] > 0.f) ? o0[q] : expm1f(o0[q]);
    *(float4*)(out + (size_t)d * HC + lane * 8)     = make_float4(o0[0], o0[1], o0[2], o0[3]);
    *(float4*)(out + (size_t)d * HC + lane * 8 + 4) = make_float4(o0[4], o0[5], o0[6], o0[7]);
}

// ---------------- launch ----------------
extern "C" void kernel_launch(void* const* d_in, const int* in_sizes, int n_in,
                              void* d_out, int out_size)
{
    const float* x   = (const float*)d_in[0];
    const int*   ei  = (const int*)  d_in[1];
    const float* W1  = (const float*)d_in[2];
    const float* as1 = (const float*)d_in[3];
    const float* ad1 = (const float*)d_in[4];
    const float* b1  = (const float*)d_in[5];
    const float* W2  = (const float*)d_in[6];
    const float* as2 = (const float*)d_in[7];
    const float* ad2 = (const float*)d_in[8];
    const float* b2  = (const float*)d_in[9];
    float* out = (float*)d_out;

    float* g_h_p;    cudaGetSymbolAddress((void**)&g_h_p,   g_h);
    float* g_mid_p;  cudaGetSymbolAddress((void**)&g_mid_p, g_mid);

    // edge sort by dst
    zero_kernel<<<(NN + 255) / 256, 256>>>();
    hist_kernel<<<(NT + 255) / 256, 256>>>(ei);
    scan_kernel<<<1, 1024>>>();
    scatter_kernel<<<(NT + 255) / 256, 256>>>(ei);

    dim3 ggrid((NN + GBM - 1) / GBM, 256 / GBN);
    const int dot_blocks  = (NN * 4 * 32 + 255) / 256;
    const int node_blocks = (NN * 32 + 255) / 256;

    // layer 1
    gemm_tf32_kernel<<<ggrid, 256>>>(x, W1, g_h_p, NN);
    dots_kernel<<<dot_blocks, 256>>>(g_h_p, as1, ad1);
    node_kernel<<<node_blocks, 256>>>(g_h_p, b1, g_mid_p);

    // layer 2
    gemm_tf32_kernel<<<ggrid, 256>>>(g_mid_p, W2, g_h_p, NN);
    dots_kernel<<<dot_blocks, 256>>>(g_h_p, as2, ad2);
    node_kernel<<<node_blocks, 256>>>(g_h_p, b2, out);
}

// round 5
// speedup vs baseline: 1.7518x; 1.0874x over previous
#include <cuda_runtime.h>
#include <math.h>

#define NN 50000          // nodes
#define NE 800000         // edges
#define NT (NN + NE)      // edges + self loops
#define HC 256            // HEADS*OUT_CH
#define NEG_SLOPE 0.2f
#define MNEG (-1.0e30f)   // finite "-inf" sentinel (avoids inf-inf=NaN in merges)

// ---------------- device scratch (no allocations allowed) ----------------
__device__ __align__(16) float g_h[NN * HC];     // current layer h = x @ W
__device__ __align__(16) float g_mid[NN * HC];   // layer-1 output (ELU'd)
__device__ __align__(16) float g_asrc[NN * 4];   // per-node, per-head src logits
__device__ __align__(16) float g_adst[NN * 4];
__device__ int g_cnt[NN];
__device__ int g_cursor[NN];
__device__ int g_start[NN + 1];
__device__ int g_srcsorted[NT];

// ---------------- small helpers ----------------
__device__ __forceinline__ float leaky(float x) { return x > 0.f ? x : NEG_SLOPE * x; }

__device__ __forceinline__ unsigned f2tf32(float f) {
    unsigned u;
    asm volatile("cvt.rna.tf32.f32 %0, %1;" : "=r"(u) : "f"(f));
    return u;
}

// ---------------- edge sort: histogram / scan / scatter ----------------
__global__ void zero_kernel() {
    int i = blockIdx.x * blockDim.x + threadIdx.x;
    if (i < NN) { g_cnt[i] = 0; g_cursor[i] = 0; }
}

__global__ void hist_kernel(const int* __restrict__ ei) {
    int i = blockIdx.x * blockDim.x + threadIdx.x;
    if (i >= NT) return;
    int d = (i < NE) ? ei[NE + i] : (i - NE);
    atomicAdd(&g_cnt[d], 1);
}

// single-block exclusive scan over g_cnt -> g_start (n = NN), 1024 threads
__global__ void scan_kernel() {
    __shared__ int warp_sums[32];
    __shared__ int s_carry;
    int tid = threadIdx.x, lane = tid & 31, wid = tid >> 5;
    if (tid == 0) s_carry = 0;
    __syncthreads();
    for (int base = 0; base < NN; base += 1024) {
        int i = base + tid;
        int v = (i < NN) ? g_cnt[i] : 0;
        int x = v;
        #pragma unroll
        for (int o = 1; o < 32; o <<= 1) {
            int y = __shfl_up_sync(0xFFFFFFFFu, x, o);
            if (lane >= o) x += y;
        }
        if (lane == 31) warp_sums[wid] = x;
        __syncthreads();
        if (wid == 0) {
            int s = warp_sums[lane];
            #pragma unroll
            for (int o = 1; o < 32; o <<= 1) {
                int y = __shfl_up_sync(0xFFFFFFFFu, s, o);
                if (lane >= o) s += y;
            }
            warp_sums[lane] = s;
        }
        __syncthreads();
        int warp_off = (wid > 0) ? warp_sums[wid - 1] : 0;
        int excl = x - v + warp_off + s_carry;
        if (i < NN) g_start[i] = excl;
        int carry_new = s_carry + warp_sums[31];
        __syncthreads();
        if (tid == 0) s_carry = carry_new;
        __syncthreads();
    }
    if (threadIdx.x == 0) g_start[NN] = s_carry;
}

__global__ void scatter_kernel(const int* __restrict__ ei) {
    int i = blockIdx.x * blockDim.x + threadIdx.x;
    if (i >= NT) return;
    int s, d;
    if (i < NE) { s = ei[i]; d = ei[NE + i]; }
    else        { s = d = i - NE; }
    int pos = g_start[d] + atomicAdd(&g_cursor[d], 1);
    g_srcsorted[pos] = s;
}

// ---------------- tf32 tensor-core GEMM + fused attention dots ------------
// C[M,256] = A[M,256] @ B[256,256]; epilogue also computes per-(node,head)
// <h, att_src> and <h, att_dst>. Warp tile 32x64 is head-aligned: head =
// blockIdx.y*2 + wn, so each warp fully owns the dot for its 32 rows.
#define GBM 128
#define GBN 128
#define GBK 32

__global__ void __launch_bounds__(256, 1) gemm_tf32_kernel(
    const float* __restrict__ A, const float* __restrict__ B,
    float* __restrict__ C, int M,
    const float* __restrict__ att_s, const float* __restrict__ att_d)
{
    __shared__ float As[GBM][GBK + 4];
    __shared__ float Bs[GBK][GBN + 4];

    int tid = threadIdx.x;
    int warp = tid >> 5, lane = tid & 31;
    int wm = warp & 3;
    int wn = warp >> 2;
    int g = lane >> 2;
    int t = lane & 3;

    int row0 = blockIdx.x * GBM;
    int col0 = blockIdx.y * GBN;

    float c[2][8][4];
    #pragma unroll
    for (int i = 0; i < 2; i++)
        #pragma unroll
        for (int j = 0; j < 8; j++)
            #pragma unroll
            for (int q = 0; q < 4; q++) c[i][j][q] = 0.f;

    float4 pa[4], pb[4];

    #pragma unroll
    for (int u = 0; u < 4; u++) {
        int slot = tid + u * 256;
        int r = slot >> 3, c4 = (slot & 7) << 2;
        int gr = row0 + r;
        pa[u] = (gr < M) ? *(const float4*)(A + (size_t)gr * 256 + c4)
                         : make_float4(0.f, 0.f, 0.f, 0.f);
        int br = slot >> 5, bc4 = (slot & 31) << 2;
        pb[u] = *(const float4*)(B + (size_t)br * 256 + col0 + bc4);
    }

    for (int kk = 0; kk < 256; kk += GBK) {
        #pragma unroll
        for (int u = 0; u < 4; u++) {
            int slot = tid + u * 256;
            int r = slot >> 3, c4 = (slot & 7) << 2;
            float4 v = pa[u];
            float4 w;
            w.x = __uint_as_float(f2tf32(v.x));
            w.y = __uint_as_float(f2tf32(v.y));
            w.z = __uint_as_float(f2tf32(v.z));
            w.w = __uint_as_float(f2tf32(v.w));
            *(float4*)&As[r][c4] = w;
            int br = slot >> 5, bc4 = (slot & 31) << 2;
            float4 b = pb[u];
            float4 bw;
            bw.x = __uint_as_float(f2tf32(b.x));
            bw.y = __uint_as_float(f2tf32(b.y));
            bw.z = __uint_as_float(f2tf32(b.z));
            bw.w = __uint_as_float(f2tf32(b.w));
            *(float4*)&Bs[br][bc4] = bw;
        }
        __syncthreads();

        if (kk + GBK < 256) {
            #pragma unroll
            for (int u = 0; u < 4; u++) {
                int slot = tid + u * 256;
                int r = slot >> 3, c4 = (slot & 7) << 2;
                int gr = row0 + r;
                pa[u] = (gr < M) ? *(const float4*)(A + (size_t)gr * 256 + kk + GBK + c4)
                                 : make_float4(0.f, 0.f, 0.f, 0.f);
                int br = slot >> 5, bc4 = (slot & 31) << 2;
                pb[u] = *(const float4*)(B + (size_t)(kk + GBK + br) * 256 + col0 + bc4);
            }
        }

        #pragma unroll
        for (int ks = 0; ks < GBK; ks += 8) {
            unsigned af[2][4];
            #pragma unroll
            for (int i = 0; i < 2; i++) {
                int m = wm * 32 + i * 16;
                af[i][0] = __float_as_uint(As[m + g][ks + t]);
                af[i][1] = __float_as_uint(As[m + 8 + g][ks + t]);
                af[i][2] = __float_as_uint(As[m + g][ks + t + 4]);
                af[i][3] = __float_as_uint(As[m + 8 + g][ks + t + 4]);
            }
            unsigned bf[8][2];
            #pragma unroll
            for (int j = 0; j < 8; j++) {
                int n = wn * 64 + j * 8;
                bf[j][0] = __float_as_uint(Bs[ks + t][n + g]);
                bf[j][1] = __float_as_uint(Bs[ks + t + 4][n + g]);
            }
            #pragma unroll
            for (int i = 0; i < 2; i++) {
                #pragma unroll
                for (int j = 0; j < 8; j++) {
                    asm volatile(
                        "mma.sync.aligned.m16n8k8.row.col.f32.tf32.tf32.f32 "
                        "{%0,%1,%2,%3}, {%4,%5,%6,%7}, {%8,%9}, {%0,%1,%2,%3};\n"
                        : "+f"(c[i][j][0]), "+f"(c[i][j][1]),
                          "+f"(c[i][j][2]), "+f"(c[i][j][3])
                        : "r"(af[i][0]), "r"(af[i][1]), "r"(af[i][2]), "r"(af[i][3]),
                          "r"(bf[j][0]), "r"(bf[j][1]));
                }
            }
        }
        __syncthreads();
    }

    // epilogue: store C and compute per-row attention dots for this head
    int head = blockIdx.y * 2 + wn;
    const float* asv = att_s + head * 64;
    const float* adv = att_d + head * 64;

    #pragma unroll
    for (int i = 0; i < 2; i++) {
        float es0 = 0.f, ed0 = 0.f, es1 = 0.f, ed1 = 0.f;
        #pragma unroll
        for (int j = 0; j < 8; j++) {
            int cc_in = j * 8 + 2 * t;           // channel within head
            float a0 = asv[cc_in], a1 = asv[cc_in + 1];
            float d0 = adv[cc_in], d1 = adv[cc_in + 1];
            es0 += c[i][j][0] * a0 + c[i][j][1] * a1;
            ed0 += c[i][j][0] * d0 + c[i][j][1] * d1;
            es1 += c[i][j][2] * a0 + c[i][j][3] * a1;
            ed1 += c[i][j][2] * d0 + c[i][j][3] * d1;

            int r0 = row0 + wm * 32 + i * 16 + g;
            int cc = col0 + wn * 64 + j * 8 + 2 * t;
            if (r0 < M)
                *(float2*)(C + (size_t)r0 * 256 + cc) = make_float2(c[i][j][0], c[i][j][1]);
            int r1 = r0 + 8;
            if (r1 < M)
                *(float2*)(C + (size_t)r1 * 256 + cc) = make_float2(c[i][j][2], c[i][j][3]);
        }
        // reduce over the 4 t-lanes (same g): lanes g*4 + {0..3}
        #pragma unroll
        for (int o = 1; o < 4; o <<= 1) {
            es0 += __shfl_xor_sync(0xFFFFFFFFu, es0, o);
            ed0 += __shfl_xor_sync(0xFFFFFFFFu, ed0, o);
            es1 += __shfl_xor_sync(0xFFFFFFFFu, es1, o);
            ed1 += __shfl_xor_sync(0xFFFFFFFFu, ed1, o);
        }
        if (t == 0) {
            int r0 = row0 + wm * 32 + i * 16 + g;
            int r1 = r0 + 8;
            if (r0 < M) { g_asrc[r0 * 4 + head] = es0; g_adst[r0 * 4 + head] = ed0; }
            if (r1 < M) { g_asrc[r1 * 4 + head] = es1; g_adst[r1 * 4 + head] = ed1; }
        }
    }
}

// ---------------- fused online softmax + aggregation + bias + ELU ----------
__global__ void __launch_bounds__(256) node_kernel(
    const float* __restrict__ h, const float* __restrict__ bias,
    float* __restrict__ out)
{
    int w = (blockIdx.x * blockDim.x + threadIdx.x) >> 5;
    int lane = threadIdx.x & 31;
    if (w >= NN) return;
    int d = w;
    int start = g_start[d], end = g_start[d + 1];

    float4 ad4 = *(const float4*)(g_adst + d * 4);

    // online softmax pass: running (max, sum) per head, strided over lanes.
    // max initialized to a large FINITE negative so empty-lane merges never
    // produce inf-inf = NaN.
    float4 m = make_float4(MNEG, MNEG, MNEG, MNEG);
    float4 sum = make_float4(0.f, 0.f, 0.f, 0.f);
    for (int j0 = start; j0 < end; j0 += 32) {
        int j = j0 + lane;
        if (j < end) {
            int s = g_srcsorted[j];
            float4 a = *(const float4*)(g_asrc + s * 4);
            float ex = leaky(a.x + ad4.x);
            float ey = leaky(a.y + ad4.y);
            float ez = leaky(a.z + ad4.z);
            float ew = leaky(a.w + ad4.w);
            float nmx = fmaxf(m.x, ex), nmy = fmaxf(m.y, ey);
            float nmz = fmaxf(m.z, ez), nmw = fmaxf(m.w, ew);
            sum.x = sum.x * __expf(m.x - nmx) + __expf(ex - nmx);
            sum.y = sum.y * __expf(m.y - nmy) + __expf(ey - nmy);
            sum.z = sum.z * __expf(m.z - nmz) + __expf(ez - nmz);
            sum.w = sum.w * __expf(m.w - nmw) + __expf(ew - nmw);
            m.x = nmx; m.y = nmy; m.z = nmz; m.w = nmw;
        }
    }
    // warp merge of (m, sum) pairs — all quantities finite by construction
    #pragma unroll
    for (int o = 16; o; o >>= 1) {
        float omx = __shfl_xor_sync(0xFFFFFFFFu, m.x, o);
        float omy = __shfl_xor_sync(0xFFFFFFFFu, m.y, o);
        float omz = __shfl_xor_sync(0xFFFFFFFFu, m.z, o);
        float omw = __shfl_xor_sync(0xFFFFFFFFu, m.w, o);
        float osx = __shfl_xor_sync(0xFFFFFFFFu, sum.x, o);
        float osy = __shfl_xor_sync(0xFFFFFFFFu, sum.y, o);
        float osz = __shfl_xor_sync(0xFFFFFFFFu, sum.z, o);
        float osw = __shfl_xor_sync(0xFFFFFFFFu, sum.w, o);
        float nmx = fmaxf(m.x, omx), nmy = fmaxf(m.y, omy);
        float nmz = fmaxf(m.z, omz), nmw = fmaxf(m.w, omw);
        sum.x = sum.x * __expf(m.x - nmx) + osx * __expf(omx - nmx);
        sum.y = sum.y * __expf(m.y - nmy) + osy * __expf(omy - nmy);
        sum.z = sum.z * __expf(m.z - nmz) + osz * __expf(omz - nmz);
        sum.w = sum.w * __expf(m.w - nmw) + osw * __expf(omw - nmw);
        m.x = nmx; m.y = nmy; m.z = nmz; m.w = nmw;
    }
    float4 inv;
    inv.x = 1.f / (sum.x + 1e-16f); inv.y = 1.f / (sum.y + 1e-16f);
    inv.z = 1.f / (sum.z + 1e-16f); inv.w = 1.f / (sum.w + 1e-16f);

    int head = lane >> 3;
    float mh   = (head == 0) ? m.x   : (head == 1) ? m.y   : (head == 2) ? m.z   : m.w;
    float invh = (head == 0) ? inv.x : (head == 1) ? inv.y : (head == 2) ? inv.z : inv.w;
    float adh  = (head == 0) ? ad4.x : (head == 1) ? ad4.y : (head == 2) ? ad4.z : ad4.w;

    // aggregation pass: unrolled x2 for MLP
    float4 acc0 = make_float4(0.f, 0.f, 0.f, 0.f);
    float4 acc1 = make_float4(0.f, 0.f, 0.f, 0.f);
    int j = start;
    for (; j + 2 <= end; j += 2) {
        int s0 = g_srcsorted[j], s1 = g_srcsorted[j + 1];
        float l0 = g_asrc[s0 * 4 + head], l1 = g_asrc[s1 * 4 + head];
        const float4* hp0 = (const float4*)(h + (size_t)s0 * HC + lane * 8);
        const float4* hp1 = (const float4*)(h + (size_t)s1 * HC + lane * 8);
        float4 p00 = hp0[0], p01 = hp0[1];
        float4 p10 = hp1[0], p11 = hp1[1];
        float w0 = __expf(leaky(l0 + adh) - mh) * invh;
        float w1 = __expf(leaky(l1 + adh) - mh) * invh;
        acc0.x += p00.x * w0; acc0.y += p00.y * w0;
        acc0.z += p00.z * w0; acc0.w += p00.w * w0;
        acc1.x += p01.x * w0; acc1.y += p01.y * w0;
        acc1.z += p01.z * w0; acc1.w += p01.w * w0;
        acc0.x += p10.x * w1; acc0.y += p10.y * w1;
        acc0.z += p10.z * w1; acc0.w += p10.w * w1;
        acc1.x += p11.x * w1; acc1.y += p11.y * w1;
        acc1.z += p11.z * w1; acc1.w += p11.w * w1;
    }
    if (j < end) {
        int s = g_srcsorted[j];
        float wgt = __expf(leaky(g_asrc[s * 4 + head] + adh) - mh) * invh;
        const float4* hp = (const float4*)(h + (size_t)s * HC + lane * 8);
        float4 p0 = hp[0], p1 = hp[1];
        acc0.x += p0.x * wgt; acc0.y += p0.y * wgt;
        acc0.z += p0.z * wgt; acc0.w += p0.w * wgt;
        acc1.x += p1.x * wgt; acc1.y += p1.y * wgt;
        acc1.z += p1.z * wgt; acc1.w += p1.w * wgt;
    }

    const float4* b4 = (const float4*)(bias + lane * 8);
    float4 b0 = b4[0], b1 = b4[1];
    float o0[8] = {acc0.x + b0.x, acc0.y + b0.y, acc0.z + b0.z, acc0.w + b0.w,
                   acc1.x + b1.x, acc1.y + b1.y, acc1.z + b1.z, acc1.w + b1.w};
    #pragma unroll
    for (int q = 0; q < 8; q++) o0[q] = (o0[q] > 0.f) ? o0[q] : expm1f(o0[q]);
    *(float4*)(out + (size_t)d * HC + lane * 8)     = make_float4(o0[0], o0[1], o0[2], o0[3]);
    *(float4*)(out + (size_t)d * HC + lane * 8 + 4) = make_float4(o0[4], o0[5], o0[6], o0[7]);
}

// ---------------- launch ----------------
extern "C" void kernel_launch(void* const* d_in, const int* in_sizes, int n_in,
                              void* d_out, int out_size)
{
    const float* x   = (const float*)d_in[0];
    const int*   ei  = (const int*)  d_in[1];
    const float* W1  = (const float*)d_in[2];
    const float* as1 = (const float*)d_in[3];
    const float* ad1 = (const float*)d_in[4];
    const float* b1  = (const float*)d_in[5];
    const float* W2  = (const float*)d_in[6];
    const float* as2 = (const float*)d_in[7];
    const float* ad2 = (const float*)d_in[8];
    const float* b2  = (const float*)d_in[9];
    float* out = (float*)d_out;

    float* g_h_p;    cudaGetSymbolAddress((void**)&g_h_p,   g_h);
    float* g_mid_p;  cudaGetSymbolAddress((void**)&g_mid_p, g_mid);

    // edge sort by dst
    zero_kernel<<<(NN + 255) / 256, 256>>>();
    hist_kernel<<<(NT + 255) / 256, 256>>>(ei);
    scan_kernel<<<1, 1024>>>();
    scatter_kernel<<<(NT + 255) / 256, 256>>>(ei);

    dim3 ggrid((NN + GBM - 1) / GBM, 256 / GBN);
    const int node_blocks = (NN * 32 + 255) / 256;

    // layer 1
    gemm_tf32_kernel<<<ggrid, 256>>>(x, W1, g_h_p, NN, as1, ad1);
    node_kernel<<<node_blocks, 256>>>(g_h_p, b1, g_mid_p);

    // layer 2
    gemm_tf32_kernel<<<ggrid, 256>>>(g_mid_p, W2, g_h_p, NN, as2, ad2);
    node_kernel<<<node_blocks, 256>>>(g_h_p, b2, out);
}